// round 5
// baseline (speedup 1.0000x reference)
#include <cuda_runtime.h>
#include <math.h>

#define BB 2
#define HH 80
#define WW 80
#define NPIX (HH * WW)

#define TW 16            // tile width  (cols, j)
#define TH 16            // tile height (rows, i)
#define NTHR (TW * TH)   // 256 threads
#define RMAX 16          // max radius supported by SMEM staging (slow path beyond)
#define RGH (TH + 2 * RMAX)   // 48 region rows
#define RGW (TW + 2 * RMAX)   // 48 region cols (float4 stride)

__device__ __forceinline__ float4 center_coef(float v0, float v1, float v2, float sg) {
    float vh = fmaxf(v0, 0.0f) + 1.0f;
    float vw = fmaxf(v1, 0.0f) + 1.0f;
    float theta = 3.14f / (1.0f + expf(-v2));      // 3.14 * sigmoid(v2)
    float s, co;
    sincosf(theta, &s, &co);
    float ivh2 = 0.5f / (vh * vh);                 // 1/(2 vh^2)
    float ivw2 = 0.5f / (vw * vw);                 // 1/(2 vw^2)
    float a  = co * co * ivh2 + s * s * ivw2;
    float b2 = 2.0f * s * co * (ivw2 - ivh2);      // 2*b of reference
    float c  = s * s * ivh2 + co * co * ivw2;
    float pen = (sg > 0.7f) ? 0.0f : 3.0e30f;
    return make_float4(a, b2, c, pen);
}

__global__ void __launch_bounds__(NTHR) fused_tile_kernel(const float* __restrict__ var,
                                                          const float* __restrict__ seg,
                                                          float* __restrict__ out) {
    __shared__ float4 s_coef[RGH * RGW];           // 36 KB
    __shared__ float s_red[NTHR / 32];
    __shared__ float s_vmax;

    const int tx = threadIdx.x;                    // 0..15
    const int ty = threadIdx.y;                    // 0..15
    const int tid = ty * TW + tx;
    const int b  = blockIdx.z;
    const int i0 = blockIdx.y * TH;
    const int j0 = blockIdx.x * TW;
    const float* vb = var + b * 3 * NPIX;
    const float* sb = seg + b * NPIX;

    // ---- 1. vmax over this batch's channels 0,1 (contiguous 2*NPIX floats) ----
    // vectorized: 2*NPIX = 12800 floats = 3200 float4 (16B-aligned: b offset is 75KiB)
    {
        const float4* v4 = reinterpret_cast<const float4*>(vb);
        float m = 0.0f;
        #pragma unroll 4
        for (int k = tid; k < 2 * NPIX / 4; k += NTHR) {
            float4 x = v4[k];
            m = fmaxf(m, fmaxf(fmaxf(x.x, x.y), fmaxf(x.z, x.w)));
        }
        #pragma unroll
        for (int o = 16; o > 0; o >>= 1)
            m = fmaxf(m, __shfl_xor_sync(0xFFFFFFFFu, m, o));
        if ((tid & 31) == 0) s_red[tid >> 5] = m;
        __syncthreads();
        if (tid == 0) {
            float bm = s_red[0];
            #pragma unroll
            for (int w = 1; w < NTHR / 32; w++) bm = fmaxf(bm, s_red[w]);
            s_vmax = fmaxf(bm, 0.0f) + 1.0f;
        }
        __syncthreads();
    }

    // E >= r^2/(2*vmax^2); relevant only if E <= -ln(0.7) ~ 0.356676 -> r <= 0.84460*vmax
    int R = (int)(0.84461f * s_vmax) + 1;
    if (R > HH - 1) R = HH - 1;

    const int i = i0 + ty;                         // this thread's output row (p)
    const int j = j0 + tx;                         // this thread's output col (q)
    float minE;

    if (R <= RMAX) {
        // ---- 2. fill SMEM with region coefficients (tile + R halo) ----
        const int r0 = max(i0 - R, 0), r1 = min(i0 + TH - 1 + R, HH - 1);
        const int c0 = max(j0 - R, 0), c1 = min(j0 + TW - 1 + R, WW - 1);
        const int rh = r1 - r0 + 1, rw = c1 - c0 + 1;
        for (int k = tid; k < rh * rw; k += NTHR) {
            int rr = k / rw;
            int cc = k - rr * rw;
            int g = (r0 + rr) * WW + (c0 + cc);
            s_coef[rr * RGW + cc] =
                center_coef(vb[g], vb[NPIX + g], vb[2 * NPIX + g], sb[g]);
        }
        __syncthreads();

        // ---- 3. windowed min over SMEM coefficients (2 accumulators, float dy) ----
        const int wr0 = max(i - R, 0), wr1 = min(i + R, HH - 1);
        const int wc0 = max(j - R, 0), wc1 = min(j + R, WW - 1);
        float m0 = 3.0e30f, m1 = 3.0e30f;
        for (int r = wr0; r <= wr1; r++) {
            float dx = (float)(i - r);
            float dx2 = dx * dx;
            const float4* row = s_coef + (r - r0) * RGW - c0;
            float dy = (float)(j - wc0);
            int cc = wc0;
            for (; cc + 1 <= wc1; cc += 2) {
                float4 k0 = row[cc];
                float4 k1 = row[cc + 1];
                float dyb = dy - 1.0f;
                float E0 = fmaf(k0.x, dx2, k0.w);
                E0 = fmaf(k0.y, dx * dy, E0);
                E0 = fmaf(k0.z, dy * dy, E0);
                float E1 = fmaf(k1.x, dx2, k1.w);
                E1 = fmaf(k1.y, dx * dyb, E1);
                E1 = fmaf(k1.z, dyb * dyb, E1);
                m0 = fminf(m0, E0);
                m1 = fminf(m1, E1);
                dy -= 2.0f;
            }
            if (cc <= wc1) {
                float4 k0 = row[cc];
                float E0 = fmaf(k0.x, dx2, k0.w);
                E0 = fmaf(k0.y, dx * dy, E0);
                E0 = fmaf(k0.z, dy * dy, E0);
                m0 = fminf(m0, E0);
            }
        }
        minE = fminf(m0, m1);
    } else {
        // ---- slow path (never triggers for sane inputs): full scan, on-the-fly coef ----
        minE = 3.0e30f;
        for (int r = 0; r < HH; r++) {
            float dx = (float)(i - r);
            float dx2 = dx * dx;
            for (int cc = 0; cc < WW; cc++) {
                int g = r * WW + cc;
                float4 k = center_coef(vb[g], vb[NPIX + g], vb[2 * NPIX + g], sb[g]);
                float dy = (float)(j - cc);
                float E = fmaf(k.x, dx2, k.w);
                E = fmaf(k.y, dx * dy, E);
                E = fmaf(k.z, dy * dy, E);
                minE = fminf(minE, E);
            }
        }
    }

    float pooled = expf(1e-7f - minE);             // exp(-minE + eps)
    out[(b * HH + i) * WW + j] = (pooled >= 0.7f) ? pooled : 0.0f;
}

extern "C" void kernel_launch(void* const* d_in, const int* in_sizes, int n_in,
                              void* d_out, int out_size) {
    const float* var = (const float*)d_in[0];   // [2,3,80,80]
    const float* seg = (const float*)d_in[1];   // [2,1,80,80]
    float* out = (float*)d_out;                 // [2,1,80,80]
    fused_tile_kernel<<<dim3(WW / TW, HH / TH, BB), dim3(TW, TH)>>>(var, seg, out);
}

// round 6
// speedup vs baseline: 1.5420x; 1.5420x over previous
#include <cuda_runtime.h>
#include <math.h>

#define BB 2
#define HH 80
#define WW 80
#define NPIX (HH * WW)

#define TW 8               // tile width  (cols, j)
#define TH 8               // tile height (rows, i)
#define NPHASE 4           // threads per pixel (window-row phases)
#define NPIXT (TW * TH)    // 64 pixels per block
#define NTHR (NPIXT * NPHASE)   // 256 threads
#define RMAX 16            // max radius supported by SMEM staging (slow path beyond)
#define RGH (TH + 2 * RMAX)     // 40 region rows
#define RGW (TW + 2 * RMAX)     // 40 region cols (float4 stride)

__device__ __forceinline__ float4 center_coef(float v0, float v1, float v2, float sg) {
    float vh = fmaxf(v0, 0.0f) + 1.0f;
    float vw = fmaxf(v1, 0.0f) + 1.0f;
    float theta = 3.14f / (1.0f + expf(-v2));      // 3.14 * sigmoid(v2)
    float s, co;
    sincosf(theta, &s, &co);
    float ivh2 = 0.5f / (vh * vh);                 // 1/(2 vh^2)
    float ivw2 = 0.5f / (vw * vw);                 // 1/(2 vw^2)
    float a  = co * co * ivh2 + s * s * ivw2;
    float b2 = 2.0f * s * co * (ivw2 - ivh2);      // 2*b of reference
    float c  = s * s * ivh2 + co * co * ivw2;
    float pen = (sg > 0.7f) ? 0.0f : 3.0e30f;
    return make_float4(a, b2, c, pen);
}

__global__ void __launch_bounds__(NTHR) fused_tile_kernel(const float* __restrict__ var,
                                                          const float* __restrict__ seg,
                                                          float* __restrict__ out) {
    __shared__ float4 s_coef[RGH * RGW];           // 25.6 KB
    __shared__ float s_red[NTHR / 32];
    __shared__ float s_vmax;
    __shared__ float s_pmin[NPHASE][NPIXT];        // per-phase partial mins

    const int tx = threadIdx.x;                    // 0..7 (col in tile)
    const int ty = threadIdx.y;                    // 0..7 (row in tile)
    const int tz = threadIdx.z;                    // 0..3 (window-row phase)
    const int pid = ty * TW + tx;                  // pixel id in tile
    const int tid = tz * NPIXT + pid;
    const int b  = blockIdx.z;
    const int i0 = blockIdx.y * TH;
    const int j0 = blockIdx.x * TW;
    const float* vb = var + b * 3 * NPIX;
    const float* sb = seg + b * NPIX;

    // ---- 1. vmax over this batch's channels 0,1 (2*NPIX = 3200 float4, 16B aligned) ----
    {
        const float4* v4 = reinterpret_cast<const float4*>(vb);
        float m = 0.0f;
        #pragma unroll 8
        for (int k = tid; k < 2 * NPIX / 4; k += NTHR) {
            float4 x = v4[k];
            m = fmaxf(m, fmaxf(fmaxf(x.x, x.y), fmaxf(x.z, x.w)));
        }
        #pragma unroll
        for (int o = 16; o > 0; o >>= 1)
            m = fmaxf(m, __shfl_xor_sync(0xFFFFFFFFu, m, o));
        if ((tid & 31) == 0) s_red[tid >> 5] = m;
        __syncthreads();
        if (tid == 0) {
            float bm = s_red[0];
            #pragma unroll
            for (int w = 1; w < NTHR / 32; w++) bm = fmaxf(bm, s_red[w]);
            s_vmax = fmaxf(bm, 0.0f) + 1.0f;
        }
        __syncthreads();
    }

    // E >= r^2/(2*vmax^2); relevant only if E <= -ln(0.7) ~ 0.356676 -> r <= 0.84460*vmax
    int R = (int)(0.84461f * s_vmax) + 1;
    if (R > HH - 1) R = HH - 1;

    const int i = i0 + ty;                         // this thread's output row (p)
    const int j = j0 + tx;                         // this thread's output col (q)
    float minE = 3.0e30f;                          // this thread's phase-partial min

    if (R <= RMAX) {
        // ---- 2. fill SMEM with region coefficients (tile + R halo) ----
        const int r0 = max(i0 - R, 0), r1 = min(i0 + TH - 1 + R, HH - 1);
        const int c0 = max(j0 - R, 0), c1 = min(j0 + TW - 1 + R, WW - 1);
        const int rh = r1 - r0 + 1, rw = c1 - c0 + 1;
        for (int k = tid; k < rh * rw; k += NTHR) {
            int rr = k / rw;
            int cc = k - rr * rw;
            int g = (r0 + rr) * WW + (c0 + cc);
            s_coef[rr * RGW + cc] =
                center_coef(vb[g], vb[NPIX + g], vb[2 * NPIX + g], sb[g]);
        }
        __syncthreads();

        // ---- 3. windowed min: phase tz handles rows wr0+tz, +NPHASE, ... ----
        const int wr0 = max(i - R, 0), wr1 = min(i + R, HH - 1);
        const int wc0 = max(j - R, 0), wc1 = min(j + R, WW - 1);
        for (int r = wr0 + tz; r <= wr1; r += NPHASE) {
            float dx = (float)(i - r);
            float dx2 = dx * dx;
            const float4* row = s_coef + (r - r0) * RGW - c0;
            #pragma unroll 4
            for (int cc = wc0; cc <= wc1; cc++) {
                float4 k = row[cc];
                float dy = (float)(j - cc);
                float E = fmaf(k.x, dx2, k.w);     // a*dx^2 + penalty
                E = fmaf(k.y, dx * dy, E);         // + 2b*dx*dy
                E = fmaf(k.z, dy * dy, E);         // + c*dy^2
                minE = fminf(minE, E);
            }
        }
    } else {
        // ---- slow path (never triggers for sane inputs): full scan, on-the-fly coef ----
        for (int r = tz; r < HH; r += NPHASE) {
            float dx = (float)(i - r);
            float dx2 = dx * dx;
            for (int cc = 0; cc < WW; cc++) {
                int g = r * WW + cc;
                float4 k = center_coef(vb[g], vb[NPIX + g], vb[2 * NPIX + g], sb[g]);
                float dy = (float)(j - cc);
                float E = fmaf(k.x, dx2, k.w);
                E = fmaf(k.y, dx * dy, E);
                E = fmaf(k.z, dy * dy, E);
                minE = fminf(minE, E);
            }
        }
    }

    // ---- 4. combine the 4 phase partials, exp + threshold, store ----
    s_pmin[tz][pid] = minE;
    __syncthreads();
    if (tz == 0) {
        float m = fminf(fminf(s_pmin[0][pid], s_pmin[1][pid]),
                        fminf(s_pmin[2][pid], s_pmin[3][pid]));
        float pooled = expf(1e-7f - m);            // exp(-minE + eps)
        out[(b * HH + i) * WW + j] = (pooled >= 0.7f) ? pooled : 0.0f;
    }
}

extern "C" void kernel_launch(void* const* d_in, const int* in_sizes, int n_in,
                              void* d_out, int out_size) {
    const float* var = (const float*)d_in[0];   // [2,3,80,80]
    const float* seg = (const float*)d_in[1];   // [2,1,80,80]
    float* out = (float*)d_out;                 // [2,1,80,80]
    fused_tile_kernel<<<dim3(WW / TW, HH / TH, BB), dim3(TW, TH, NPHASE)>>>(var, seg, out);
}

// round 7
// speedup vs baseline: 1.6579x; 1.0752x over previous
#include <cuda_runtime.h>
#include <math.h>

#define BB 2
#define HH 80
#define WW 80
#define NPIX (HH * WW)

#define TW 8               // tile width  (cols, j)
#define TH 8               // tile height (rows, i)
#define NPHASE 4           // threads per pixel (window-row phases)
#define NPIXT (TW * TH)    // 64 pixels per block
#define NTHR (NPIXT * NPHASE)   // 256 threads
#define NWARP (NTHR / 32)  // 8
#define RMAX 16            // max radius supported by SMEM staging (slow path beyond)
#define RGH (TH + 2 * RMAX)     // 40 region rows
#define RGW (TW + 2 * RMAX)     // 40 region cols (float4 stride)

__device__ __forceinline__ float4 center_coef(float v0, float v1, float v2, float sg) {
    float vh = fmaxf(v0, 0.0f) + 1.0f;
    float vw = fmaxf(v1, 0.0f) + 1.0f;
    float theta = 3.14f / (1.0f + expf(-v2));      // 3.14 * sigmoid(v2)
    float s, co;
    sincosf(theta, &s, &co);
    float ivh2 = 0.5f / (vh * vh);                 // 1/(2 vh^2)
    float ivw2 = 0.5f / (vw * vw);                 // 1/(2 vw^2)
    float a  = co * co * ivh2 + s * s * ivw2;
    float b2 = 2.0f * s * co * (ivw2 - ivh2);      // 2*b of reference
    float c  = s * s * ivh2 + co * co * ivw2;
    float pen = (sg > 0.7f) ? 0.0f : 3.0e30f;
    return make_float4(a, b2, c, pen);
}

__global__ void __launch_bounds__(NTHR) fused_tile_kernel(const float* __restrict__ var,
                                                          const float* __restrict__ seg,
                                                          float* __restrict__ out) {
    __shared__ float4 s_coef[RGH * RGW];           // 25.6 KB
    __shared__ float s_red[NWARP];
    __shared__ float s_pmin[NPHASE][NPIXT];        // per-phase partial mins

    const int tx = threadIdx.x;                    // 0..7 (col in tile)
    const int ty = threadIdx.y;                    // 0..7 (row in tile)
    const int tz = threadIdx.z;                    // 0..3 (window-row phase)
    const int pid = ty * TW + tx;                  // pixel id in tile
    const int tid = tz * NPIXT + pid;
    const int b  = blockIdx.z;
    const int i0 = blockIdx.y * TH;
    const int j0 = blockIdx.x * TW;
    const float* vb = var + b * 3 * NPIX;
    const float* sb = seg + b * NPIX;

    // ---- 1. vmax over this batch's channels 0,1: 3200 float4 = 256*12 + 128 ----
    // 12 unconditional + 1 conditional independent loads -> single L2 latency exposure.
    {
        const float4* v4 = reinterpret_cast<const float4*>(vb);
        float4 x[13];
        #pragma unroll
        for (int u = 0; u < 12; u++) x[u] = v4[tid + u * NTHR];
        bool extra = tid < 128;
        if (extra) x[12] = v4[3072 + tid];
        float m = 0.0f;
        #pragma unroll
        for (int u = 0; u < 12; u++)
            m = fmaxf(m, fmaxf(fmaxf(x[u].x, x[u].y), fmaxf(x[u].z, x[u].w)));
        if (extra)
            m = fmaxf(m, fmaxf(fmaxf(x[12].x, x[12].y), fmaxf(x[12].z, x[12].w)));
        // warp max via REDUX (m >= 0 -> uint bit order == float order)
        m = __uint_as_float(__reduce_max_sync(0xFFFFFFFFu, __float_as_uint(m)));
        if ((tid & 31) == 0) s_red[tid >> 5] = m;
    }
    __syncthreads();

    // every thread reduces the 8 per-warp maxima itself (broadcast LDS, no extra sync)
    float vmax;
    {
        float bm = s_red[0];
        #pragma unroll
        for (int w = 1; w < NWARP; w++) bm = fmaxf(bm, s_red[w]);
        vmax = fmaxf(bm, 0.0f) + 1.0f;
    }

    // E >= r^2/(2*vmax^2); relevant only if E <= -ln(0.7) ~ 0.356676 -> r <= 0.84460*vmax
    int R = (int)(0.84461f * vmax) + 1;
    if (R > HH - 1) R = HH - 1;

    const int i = i0 + ty;                         // this thread's output row (p)
    const int j = j0 + tx;                         // this thread's output col (q)
    float minE = 3.0e30f;                          // this thread's phase-partial min

    if (R <= RMAX) {
        // ---- 2. fill SMEM with region coefficients (tile + R halo) ----
        const int r0 = max(i0 - R, 0), r1 = min(i0 + TH - 1 + R, HH - 1);
        const int c0 = max(j0 - R, 0), c1 = min(j0 + TW - 1 + R, WW - 1);
        const int rh = r1 - r0 + 1, rw = c1 - c0 + 1;
        for (int k = tid; k < rh * rw; k += NTHR) {
            int rr = k / rw;
            int cc = k - rr * rw;
            int g = (r0 + rr) * WW + (c0 + cc);
            s_coef[rr * RGW + cc] =
                center_coef(vb[g], vb[NPIX + g], vb[2 * NPIX + g], sb[g]);
        }
        __syncthreads();

        // ---- 3. windowed min: phase tz handles rows wr0+tz, +NPHASE, ... ----
        const int wr0 = max(i - R, 0), wr1 = min(i + R, HH - 1);
        const int wc0 = max(j - R, 0), wc1 = min(j + R, WW - 1);
        const float dy0 = (float)(j - wc0);
        for (int r = wr0 + tz; r <= wr1; r += NPHASE) {
            float dx = (float)(i - r);
            float dx2 = dx * dx;
            const float4* row = s_coef + (r - r0) * RGW - c0;
            float dy = dy0;
            #pragma unroll 4
            for (int cc = wc0; cc <= wc1; cc++) {
                float4 k = row[cc];
                float E = fmaf(k.x, dx2, k.w);     // a*dx^2 + penalty
                E = fmaf(k.y, dx * dy, E);         // + 2b*dx*dy
                E = fmaf(k.z, dy * dy, E);         // + c*dy^2
                minE = fminf(minE, E);
                dy -= 1.0f;
            }
        }
    } else {
        // ---- slow path (never triggers for sane inputs): full scan, on-the-fly coef ----
        for (int r = tz; r < HH; r += NPHASE) {
            float dx = (float)(i - r);
            float dx2 = dx * dx;
            for (int cc = 0; cc < WW; cc++) {
                int g = r * WW + cc;
                float4 k = center_coef(vb[g], vb[NPIX + g], vb[2 * NPIX + g], sb[g]);
                float dy = (float)(j - cc);
                float E = fmaf(k.x, dx2, k.w);
                E = fmaf(k.y, dx * dy, E);
                E = fmaf(k.z, dy * dy, E);
                minE = fminf(minE, E);
            }
        }
    }

    // ---- 4. combine the 4 phase partials, exp + threshold, store ----
    s_pmin[tz][pid] = minE;
    __syncthreads();
    if (tz == 0) {
        float m = fminf(fminf(s_pmin[0][pid], s_pmin[1][pid]),
                        fminf(s_pmin[2][pid], s_pmin[3][pid]));
        float pooled = expf(1e-7f - m);            // exp(-minE + eps)
        out[(b * HH + i) * WW + j] = (pooled >= 0.7f) ? pooled : 0.0f;
    }
}

extern "C" void kernel_launch(void* const* d_in, const int* in_sizes, int n_in,
                              void* d_out, int out_size) {
    const float* var = (const float*)d_in[0];   // [2,3,80,80]
    const float* seg = (const float*)d_in[1];   // [2,1,80,80]
    float* out = (float*)d_out;                 // [2,1,80,80]
    fused_tile_kernel<<<dim3(WW / TW, HH / TH, BB), dim3(TW, TH, NPHASE)>>>(var, seg, out);
}

// round 8
// speedup vs baseline: 1.7160x; 1.0350x over previous
#include <cuda_runtime.h>
#include <math.h>

#define BB 2
#define HH 80
#define WW 80
#define NPIX (HH * WW)

#define TW 8               // tile width  (cols, j)
#define TH 8               // tile height (rows, i)
#define NPHASE 4           // threads per pixel (window-row phases)
#define NPIXT (TW * TH)    // 64 pixels per block
#define NTHR (NPIXT * NPHASE)   // 256 threads
#define NWARP (NTHR / 32)  // 8
#define RMAX 16            // largest templated radius (slow path beyond)

__device__ __forceinline__ float4 center_coef(float v0, float v1, float v2, float sg) {
    float vh = fmaxf(v0, 0.0f) + 1.0f;
    float vw = fmaxf(v1, 0.0f) + 1.0f;
    float theta = __fdividef(3.14f, 1.0f + __expf(-v2));   // 3.14 * sigmoid(v2)
    float s, co;
    __sincosf(theta, &s, &co);
    float ivh2 = __fdividef(0.5f, vh * vh);                // 1/(2 vh^2)
    float ivw2 = __fdividef(0.5f, vw * vw);                // 1/(2 vw^2)
    float a  = co * co * ivh2 + s * s * ivw2;
    float b2 = 2.0f * s * co * (ivw2 - ivh2);              // 2*b of reference
    float c  = s * s * ivh2 + co * co * ivw2;
    float pen = (sg > 0.7f) ? 0.0f : 3.0e30f;
    return make_float4(a, b2, c, pen);
}

// Fixed-radius path: region = (TH+2RP) x (TW+2RP) centers around the tile,
// out-of-image cells carry penalty 3e30. Window bounds are compile-time.
template <int RP>
__device__ __forceinline__ float window_min(float4* s_coef,
                                            const float* vb, const float* sb,
                                            int i0, int j0,
                                            int tid, int tx, int ty, int tz) {
    constexpr int RH = TH + 2 * RP;
    constexpr int RW = TW + 2 * RP;

    // ---- fill region (uniform, sentinel-padded) ----
    for (int k = tid; k < RH * RW; k += NTHR) {
        int rr = k / RW;                        // RW compile-time -> mul/shift
        int cc = k - rr * RW;
        int r = i0 - RP + rr;
        int c = j0 - RP + cc;
        float4 v;
        if (r >= 0 && r < HH && c >= 0 && c < WW) {
            int g = r * WW + c;
            v = center_coef(vb[g], vb[NPIX + g], vb[2 * NPIX + g], sb[g]);
        } else {
            v = make_float4(0.0f, 0.0f, 0.0f, 3.0e30f);
        }
        s_coef[k] = v;
    }
    __syncthreads();

    // ---- windowed min: candidate region rows ty..ty+2RP, cols tx..tx+2RP ----
    // dx = RP - rr, dy = RP - cc : compile-time constants.
    float minE = 3.0e30f;
    #pragma unroll
    for (int rr = tz; rr <= 2 * RP; rr += NPHASE) {
        const float dx = (float)(RP - rr);
        const float dx2 = dx * dx;
        const float4* row = s_coef + (ty + rr) * RW + tx;
        #pragma unroll
        for (int cc = 0; cc <= 2 * RP; cc++) {
            const float dy = (float)(RP - cc);
            float4 k = row[cc];
            float E = fmaf(k.x, dx2, k.w);      // a*dx^2 + penalty
            E = fmaf(k.y, dx * dy, E);          // + 2b*dx*dy
            E = fmaf(k.z, dy * dy, E);          // + c*dy^2
            minE = fminf(minE, E);
        }
    }
    return minE;
}

__global__ void __launch_bounds__(NTHR) fused_tile_kernel(const float* __restrict__ var,
                                                          const float* __restrict__ seg,
                                                          float* __restrict__ out) {
    __shared__ float4 s_coef[(TH + 2 * RMAX) * (TW + 2 * RMAX)];   // 25.6 KB (max path)
    __shared__ float s_red[NWARP];
    __shared__ float s_pmin[NPHASE][NPIXT];

    const int tx = threadIdx.x;                 // 0..7 (col in tile)
    const int ty = threadIdx.y;                 // 0..7 (row in tile)
    const int tz = threadIdx.z;                 // 0..3 (window-row phase)
    const int pid = ty * TW + tx;
    const int tid = tz * NPIXT + pid;
    const int b  = blockIdx.z;
    const int i0 = blockIdx.y * TH;
    const int j0 = blockIdx.x * TW;
    const float* vb = var + b * 3 * NPIX;
    const float* sb = seg + b * NPIX;

    // ---- 1. vmax over this batch's channels 0,1: 3200 float4 = 256*12 + 128 ----
    {
        const float4* v4 = reinterpret_cast<const float4*>(vb);
        float4 x[13];
        #pragma unroll
        for (int u = 0; u < 12; u++) x[u] = v4[tid + u * NTHR];
        bool extra = tid < 128;
        if (extra) x[12] = v4[3072 + tid];
        float m = 0.0f;
        #pragma unroll
        for (int u = 0; u < 12; u++)
            m = fmaxf(m, fmaxf(fmaxf(x[u].x, x[u].y), fmaxf(x[u].z, x[u].w)));
        if (extra)
            m = fmaxf(m, fmaxf(fmaxf(x[12].x, x[12].y), fmaxf(x[12].z, x[12].w)));
        m = __uint_as_float(__reduce_max_sync(0xFFFFFFFFu, __float_as_uint(m)));
        if ((tid & 31) == 0) s_red[tid >> 5] = m;
    }
    __syncthreads();

    float vmax;
    {
        float bm = s_red[0];
        #pragma unroll
        for (int w = 1; w < NWARP; w++) bm = fmaxf(bm, s_red[w]);
        vmax = fmaxf(bm, 0.0f) + 1.0f;
    }

    // E >= r^2/(2*vmax^2); relevant only if E <= -ln(0.7) ~ 0.356676 -> r <= 0.84460*vmax
    int R = (int)(0.84461f * vmax) + 1;

    const int i = i0 + ty;
    const int j = j0 + tx;
    float minE;

    if (R <= 6) {
        minE = window_min<6>(s_coef, vb, sb, i0, j0, tid, tx, ty, tz);
    } else if (R <= 10) {
        minE = window_min<10>(s_coef, vb, sb, i0, j0, tid, tx, ty, tz);
    } else if (R <= RMAX) {
        minE = window_min<RMAX>(s_coef, vb, sb, i0, j0, tid, tx, ty, tz);
    } else {
        // slow path (never triggers for sane inputs): full scan, on-the-fly coef
        minE = 3.0e30f;
        for (int r = tz; r < HH; r += NPHASE) {
            float dx = (float)(i - r);
            float dx2 = dx * dx;
            for (int cc = 0; cc < WW; cc++) {
                int g = r * WW + cc;
                float4 k = center_coef(vb[g], vb[NPIX + g], vb[2 * NPIX + g], sb[g]);
                float dy = (float)(j - cc);
                float E = fmaf(k.x, dx2, k.w);
                E = fmaf(k.y, dx * dy, E);
                E = fmaf(k.z, dy * dy, E);
                minE = fminf(minE, E);
            }
        }
    }

    // ---- combine phase partials, exp + threshold, store ----
    s_pmin[tz][pid] = minE;
    __syncthreads();
    if (tz == 0) {
        float m = fminf(fminf(s_pmin[0][pid], s_pmin[1][pid]),
                        fminf(s_pmin[2][pid], s_pmin[3][pid]));
        float pooled = __expf(1e-7f - m);        // exp(-minE + eps)
        out[(b * HH + i) * WW + j] = (pooled >= 0.7f) ? pooled : 0.0f;
    }
}

extern "C" void kernel_launch(void* const* d_in, const int* in_sizes, int n_in,
                              void* d_out, int out_size) {
    const float* var = (const float*)d_in[0];   // [2,3,80,80]
    const float* seg = (const float*)d_in[1];   // [2,1,80,80]
    float* out = (float*)d_out;                 // [2,1,80,80]
    fused_tile_kernel<<<dim3(WW / TW, HH / TH, BB), dim3(TW, TH, NPHASE)>>>(var, seg, out);
}